// round 17
// baseline (speedup 1.0000x reference)
#include <cuda_runtime.h>
#include <cuda_fp16.h>
#include <cstdint>
#include <math.h>

#define B_SZ 64
#define N_SZ 512
#define H_SZ 512
#define NQ 8
#define NLAYERS 4

#define KCHUNK 64
#define TILE_BYTES 16384                // 16KB per operand tile
#define STAGE_BYTES (2 * TILE_BYTES)    // 32KB: A + B
#define NSTAGE 3
#define SMEM_GEMM (NSTAGE * STAGE_BYTES)   // 96KB -> 2 CTAs/SM
#define NTHREADS 256
#define NPERSIST 296                    // 2 x 148 SMs
#define NTILES 1024

// ---------------------------------------------------------------------------
// Static scratch (no allocs allowed)
// ---------------------------------------------------------------------------
__device__ __half g_x16[(size_t)B_SZ * N_SZ * H_SZ];  // rounded fp16, [b,j,h]
__device__ __half g_adj[N_SZ * N_SZ];                 // rounded fp16
__device__ __half g_W[H_SZ * H_SZ];                   // rounded fp16
__device__ __half g_g1[(size_t)B_SZ * N_SZ * H_SZ];   // fp16

// ---------------------------------------------------------------------------
// helpers
// ---------------------------------------------------------------------------
__device__ __forceinline__ uint32_t smem_u32(const void* p) {
    uint32_t a;
    asm("{ .reg .u64 t; cvta.to.shared.u64 t, %1; cvt.u32.u64 %0, t; }" : "=r"(a) : "l"(p));
    return a;
}
// SW128 swizzle (bits[6:4] ^= bits[9:7]) — for 128B rows
__device__ __forceinline__ uint32_t swz(uint32_t o) { return o ^ ((o >> 3) & 0x70); }

__device__ __forceinline__ void cp16(uint32_t dst, const void* src) {
    asm volatile("cp.async.cg.shared.global [%0], [%1], 16;" :: "r"(dst), "l"(src));
}
__device__ __forceinline__ void ldsm4(uint32_t* r, uint32_t addr) {
    asm volatile("ldmatrix.sync.aligned.m8n8.x4.shared.b16 {%0,%1,%2,%3}, [%4];"
                 : "=r"(r[0]), "=r"(r[1]), "=r"(r[2]), "=r"(r[3]) : "r"(addr));
}
__device__ __forceinline__ void ldsm4t(uint32_t* r, uint32_t addr) {
    asm volatile("ldmatrix.sync.aligned.m8n8.x4.trans.shared.b16 {%0,%1,%2,%3}, [%4];"
                 : "=r"(r[0]), "=r"(r[1]), "=r"(r[2]), "=r"(r[3]) : "r"(addr));
}
__device__ __forceinline__ void mma_f16(float* c, const uint32_t* a, const uint32_t* b) {
    asm volatile(
        "mma.sync.aligned.m16n8k16.row.col.f32.f16.f16.f32 "
        "{%0,%1,%2,%3}, {%4,%5,%6,%7}, {%8,%9}, {%0,%1,%2,%3};"
        : "+f"(c[0]), "+f"(c[1]), "+f"(c[2]), "+f"(c[3])
        : "r"(a[0]), "r"(a[1]), "r"(a[2]), "r"(a[3]), "r"(b[0]), "r"(b[1]));
}

// ---------------------------------------------------------------------------
// Conversion kernels
// ---------------------------------------------------------------------------
// x fp32 -> fp16, fully coalesced (no transpose). 8 elems/thread.
__global__ void conv_x_kernel(const float* __restrict__ x) {
    const size_t i = ((size_t)blockIdx.x * 256 + threadIdx.x) * 8;
    float4 v0 = *(const float4*)(x + i);
    float4 v1 = *(const float4*)(x + i + 4);
    __half2 h[4];
    h[0] = __floats2half2_rn(v0.x, v0.y);
    h[1] = __floats2half2_rn(v0.z, v0.w);
    h[2] = __floats2half2_rn(v1.x, v1.y);
    h[3] = __floats2half2_rn(v1.z, v1.w);
    *(uint4*)(g_x16 + i) = *(uint4*)h;
}

// adj and W -> single fp16 planes
__global__ void conv_small_kernel(const float* __restrict__ adj,
                                  const float* __restrict__ W) {
    int base = blockIdx.x * 1024 + threadIdx.x;
    const float* src = (blockIdx.y == 0) ? adj : W;
    __half* dst = (blockIdx.y == 0) ? g_adj : g_W;
#pragma unroll
    for (int i = 0; i < 4; i++) {
        int idx = base + i * 256;
        dst[idx] = __float2half(src[idx]);
    }
}

// ---------------------------------------------------------------------------
// GEMM plumbing.  CTA tile 128x128, 8 warps (2x4), warp tile 64x32.
// BT=false: B tile stored [n=128 rows][128B k-rows] (K-major, non-trans ldsm)
// BT=true : B tile stored [k=64 rows][256B n-rows] (natural x layout, trans)
// ---------------------------------------------------------------------------
template <bool BT>
__device__ __forceinline__ void prefetch_chunk(
    uint32_t sb, int stage, int kc, int tid,
    const __half* __restrict__ A, const __half* __restrict__ B) {
    const uint32_t base = sb + stage * STAGE_BYTES;
    const __half* As = A + kc * KCHUNK;
#pragma unroll
    for (int i = 0; i < 4; i++) {          // A: 1024 16B-chunks, 128B rows
        const int j = tid + i * NTHREADS;
        const int row = j >> 3, c = j & 7;
        cp16(base + swz(row * 128 + c * 16), As + (size_t)row * 512 + c * 8);
    }
    if (BT) {
        // B: 64 k-rows x 256B, row-local XOR swizzle
        const __half* Bs = B + (size_t)kc * KCHUNK * 512;
#pragma unroll
        for (int i = 0; i < 4; i++) {
            const int j = tid + i * NTHREADS;  // 0..1023
            const int row = j >> 4, c = j & 15;
            cp16(base + TILE_BYTES + row * 256 + ((c ^ (row & 7)) * 16),
                 Bs + (size_t)row * 512 + c * 8);
        }
    } else {
        const __half* Bs = B + kc * KCHUNK;
#pragma unroll
        for (int i = 0; i < 4; i++) {
            const int j = tid + i * NTHREADS;
            const int row = j >> 3, c = j & 7;
            cp16(base + TILE_BYTES + swz(row * 128 + c * 16),
                 Bs + (size_t)row * 512 + c * 8);
        }
    }
    asm volatile("cp.async.commit_group;");
}

// fp16 MMA over one 128x128x64 chunk. Warp computes 64x32.
template <bool BT>
__device__ __forceinline__ void compute_chunk(uint32_t sb, int stage, int wid, int lane,
                                              float acc[4][4][4]) {
    const uint32_t base = sb + stage * STAGE_BYTES;
    const int m0 = (wid & 1) * 64;
    const int n0 = (wid >> 1) * 32;
    const int ar = (lane & 7) + ((lane >> 3) & 1) * 8;
    const int ac = ((lane >> 4) & 1) * 8;
    const int br = (lane & 7) + ((lane >> 4) & 1) * 8;
    const int bc = ((lane >> 3) & 1) * 8;
    const int krow_lo = ((lane >> 3) & 1) * 8 + (lane & 7);
    const int nsel = ((lane >> 4) & 1) * 8;
#pragma unroll
    for (int ks = 0; ks < 4; ks++) {
        uint32_t a[4][4], b[4][2];
#pragma unroll
        for (int mt = 0; mt < 4; mt++) {
            const uint32_t off = swz((m0 + mt * 16 + ar) * 128 + (ks * 16 + ac) * 2);
            ldsm4(a[mt], base + off);
        }
#pragma unroll
        for (int nt2 = 0; nt2 < 2; nt2++) {
            uint32_t r[4];
            if (BT) {
                const int n_off = n0 + nt2 * 16 + nsel;
                const int krow = ks * 16 + krow_lo;
                const uint32_t off = krow * 256 + (((n_off >> 3) ^ (krow & 7)) * 16);
                ldsm4t(r, base + TILE_BYTES + off);
            } else {
                const uint32_t off = swz((n0 + nt2 * 16 + br) * 128 + (ks * 16 + bc) * 2);
                ldsm4(r, base + TILE_BYTES + off);
            }
            b[nt2 * 2][0] = r[0]; b[nt2 * 2][1] = r[1];
            b[nt2 * 2 + 1][0] = r[2]; b[nt2 * 2 + 1][1] = r[3];
        }
#pragma unroll
        for (int mt = 0; mt < 4; mt++)
#pragma unroll
            for (int nt = 0; nt < 4; nt++)
                mma_f16(acc[mt][nt], a[mt], b[nt]);
    }
}

// ---------------------------------------------------------------------------
// GEMM1 (persistent, flat pipeline): g1 = adj @ x  -> fp16.
// tiles: (b:64) x (i:4) x (h:4) = 1024.  grid = NPERSIST.
// ---------------------------------------------------------------------------
__global__ __launch_bounds__(NTHREADS, 2) void gemm1_mma_kernel() {
    extern __shared__ __align__(128) char smem[];
    const uint32_t sb = smem_u32(smem);
    const int tid = threadIdx.x, wid = tid >> 5, lane = tid & 31;

    // my tiles
    int myt[4];
    int n_my = 0;
#pragma unroll 1
    for (int t = blockIdx.x; t < NTILES; t += NPERSIST) myt[n_my++] = t;
    const int P = n_my * 8;
    if (P == 0) return;

    auto srcA = [&](int tile) {
        return g_adj + (size_t)(((tile >> 2) & 3) * 128) * 512;
    };
    auto srcB = [&](int tile) {
        return g_x16 + (size_t)(tile >> 4) * 512 * 512 + (tile & 3) * 128;
    };

    prefetch_chunk<true>(sb, 0, 0, tid, srcA(myt[0]), srcB(myt[0]));
    prefetch_chunk<true>(sb, 1, 1, tid, srcA(myt[0]), srcB(myt[0]));

    float acc[4][4][4];
#pragma unroll
    for (int i = 0; i < 4; i++)
#pragma unroll
        for (int j = 0; j < 4; j++)
#pragma unroll
            for (int k = 0; k < 4; k++) acc[i][j][k] = 0.f;

#pragma unroll 1
    for (int p = 0; p < P; p++) {
        if (p >= P - 2) asm volatile("cp.async.wait_group 0;");
        else            asm volatile("cp.async.wait_group 1;");
        __syncthreads();
        if (p + 2 < P) {
            const int q = p + 2;
            const int qt = myt[q >> 3];
            prefetch_chunk<true>(sb, q % NSTAGE, q & 7, tid, srcA(qt), srcB(qt));
        }
        compute_chunk<true>(sb, p % NSTAGE, wid, lane, acc);

        if ((p & 7) == 7) {
            const int tile = myt[p >> 3];
            const int b = tile >> 4;
            const int iBase = ((tile >> 2) & 3) * 128;
            const int hBase = (tile & 3) * 128;
            const int m0 = (wid & 1) * 64, n0 = (wid >> 1) * 32;
            const int g = lane >> 2, t = lane & 3;
#pragma unroll
            for (int mt = 0; mt < 4; mt++)
#pragma unroll
                for (int nt = 0; nt < 4; nt++) {
                    const int r0 = iBase + m0 + mt * 16 + g;
                    const int col = hBase + n0 + nt * 8 + t * 2;
                    const size_t o0 = ((size_t)b * 512 + r0) * 512 + col;
                    const size_t o1 = o0 + (size_t)8 * 512;
                    __half2 v0, v1;
                    v0.x = __float2half(acc[mt][nt][0]);
                    v0.y = __float2half(acc[mt][nt][1]);
                    v1.x = __float2half(acc[mt][nt][2]);
                    v1.y = __float2half(acc[mt][nt][3]);
                    *(__half2*)(g_g1 + o0) = v0;
                    *(__half2*)(g_g1 + o1) = v1;
                    acc[mt][nt][0] = 0.f; acc[mt][nt][1] = 0.f;
                    acc[mt][nt][2] = 0.f; acc[mt][nt][3] = 0.f;
                }
        }
    }
}

// ---------------------------------------------------------------------------
// GEMM2 (persistent, flat pipeline) + bias + exact GELU.
// tiles: (m:256) x (n:4) = 1024.
// ---------------------------------------------------------------------------
__device__ __forceinline__ float gelu_exact(float v) {
    return 0.5f * v * (1.0f + erff(v * 0.70710678118654752440f));
}

__global__ __launch_bounds__(NTHREADS, 2) void gemm2_mma_kernel(const float* __restrict__ bias,
                                                                float* __restrict__ out) {
    extern __shared__ __align__(128) char smem[];
    const uint32_t sb = smem_u32(smem);
    const int tid = threadIdx.x, wid = tid >> 5, lane = tid & 31;

    int myt[4];
    int n_my = 0;
#pragma unroll 1
    for (int t = blockIdx.x; t < NTILES; t += NPERSIST) myt[n_my++] = t;
    const int P = n_my * 8;
    if (P == 0) return;

    auto srcA = [&](int tile) { return g_g1 + (size_t)(tile >> 2) * 128 * 512; };
    auto srcB = [&](int tile) { return g_W + (size_t)(tile & 3) * 128 * 512; };

    prefetch_chunk<false>(sb, 0, 0, tid, srcA(myt[0]), srcB(myt[0]));
    prefetch_chunk<false>(sb, 1, 1, tid, srcA(myt[0]), srcB(myt[0]));

    float acc[4][4][4];
#pragma unroll
    for (int i = 0; i < 4; i++)
#pragma unroll
        for (int j = 0; j < 4; j++)
#pragma unroll
            for (int k = 0; k < 4; k++) acc[i][j][k] = 0.f;

#pragma unroll 1
    for (int p = 0; p < P; p++) {
        if (p >= P - 2) asm volatile("cp.async.wait_group 0;");
        else            asm volatile("cp.async.wait_group 1;");
        __syncthreads();
        if (p + 2 < P) {
            const int q = p + 2;
            const int qt = myt[q >> 3];
            prefetch_chunk<false>(sb, q % NSTAGE, q & 7, tid, srcA(qt), srcB(qt));
        }
        compute_chunk<false>(sb, p % NSTAGE, wid, lane, acc);

        if ((p & 7) == 7) {
            const int tile = myt[p >> 3];
            const int mBase = (tile >> 2) * 128;
            const int nBase = (tile & 3) * 128;
            const int m0 = (wid & 1) * 64, n0 = (wid >> 1) * 32;
            const int g = lane >> 2, t = lane & 3;
#pragma unroll
            for (int mt = 0; mt < 4; mt++)
#pragma unroll
                for (int nt = 0; nt < 4; nt++) {
                    const int r0 = mBase + m0 + mt * 16 + g;
                    const int col = nBase + n0 + nt * 8 + t * 2;
                    const float b0 = __ldg(bias + col), b1 = __ldg(bias + col + 1);
                    float2 v0, v1;
                    v0.x = gelu_exact(acc[mt][nt][0] + b0);
                    v0.y = gelu_exact(acc[mt][nt][1] + b1);
                    v1.x = gelu_exact(acc[mt][nt][2] + b0);
                    v1.y = gelu_exact(acc[mt][nt][3] + b1);
                    *(float2*)(out + (size_t)r0 * 512 + col) = v0;
                    *(float2*)(out + (size_t)(r0 + 8) * 512 + col) = v1;
                    acc[mt][nt][0] = 0.f; acc[mt][nt][1] = 0.f;
                    acc[mt][nt][2] = 0.f; acc[mt][nt][3] = 0.f;
                }
        }
    }
}

// ---------------------------------------------------------------------------
// Quantum circuit + pre/post projections (one block per batch element)
// ---------------------------------------------------------------------------
__global__ void quantum_kernel(const float* __restrict__ pre_w,
                               const float* __restrict__ pre_b,
                               const float* __restrict__ post_w,
                               const float* __restrict__ post_b,
                               const float* __restrict__ qw,
                               float* __restrict__ out) {
    const int b = blockIdx.x;
    const int tid = threadIdx.x;
    const int warp = tid >> 5;
    const int lane = tid & 31;

    __shared__ float angles[NQ];
    __shared__ float sre[256], sim_[256];
    __shared__ float probs[256];
    __shared__ float zs[NQ];

    const float* tgt = out + (size_t)b * N_SZ * H_SZ;

    {
        float partial = 0.f;
        const float* pw = pre_w + warp * H_SZ;
        for (int k = lane; k < H_SZ; k += 32) partial += tgt[k] * pw[k];
#pragma unroll
        for (int o = 16; o; o >>= 1) partial += __shfl_down_sync(0xffffffffu, partial, o);
        if (lane == 0)
            angles[warp] = tanhf(partial + pre_b[warp]) * 3.14159265358979323846f;
    }

    sre[tid] = (tid == 0) ? 1.f : 0.f;
    sim_[tid] = 0.f;
    __syncthreads();

    for (int w = 0; w < NQ; w++) {
        const int mask = 1 << (7 - w);
        const float th = angles[w] * 0.5f;
        const float c = cosf(th), s = sinf(th);
        if (tid < 128) {
            const int i0 = ((tid & ~(mask - 1)) << 1) | (tid & (mask - 1));
            const int i1 = i0 | mask;
            float a0r = sre[i0], a0i = sim_[i0];
            float a1r = sre[i1], a1i = sim_[i1];
            sre[i0] = c * a0r - s * a1r;
            sim_[i0] = c * a0i - s * a1i;
            sre[i1] = s * a0r + c * a1r;
            sim_[i1] = s * a0i + c * a1i;
        }
        __syncthreads();
    }

    for (int l = 0; l < NLAYERS; l++) {
        for (int w = 0; w < NQ; w++) {
            const int mask = 1 << (7 - w);
            const float th = qw[l * NQ + w] * 0.5f;
            const float c = cosf(th), s = sinf(th);
            if (tid < 128) {
                const int i0 = ((tid & ~(mask - 1)) << 1) | (tid & (mask - 1));
                const int i1 = i0 | mask;
                float a0r = sre[i0], a0i = sim_[i0];
                float a1r = sre[i1], a1i = sim_[i1];
                sre[i0] = c * a0r + s * a1i;
                sim_[i0] = c * a0i - s * a1r;
                sre[i1] = c * a1r + s * a0i;
                sim_[i1] = c * a1i - s * a0r;
            }
            __syncthreads();
        }
        for (int w = 0; w < NQ; w++) {
            const int t = (w + 1) & 7;
            const int mc = 1 << (7 - w);
            const int mt = 1 << (7 - t);
            const int src = (tid & mc) ? (tid ^ mt) : tid;
            const float vr = sre[src], vi = sim_[src];
            __syncthreads();
            sre[tid] = vr;
            sim_[tid] = vi;
            __syncthreads();
        }
    }

    probs[tid] = sre[tid] * sre[tid] + sim_[tid] * sim_[tid];
    __syncthreads();
    {
        const int m = 1 << (7 - warp);
        float z = 0.f;
        for (int i = lane; i < 256; i += 32)
            z += (i & m) ? -probs[i] : probs[i];
#pragma unroll
        for (int o = 16; o; o >>= 1) z += __shfl_down_sync(0xffffffffu, z, o);
        if (lane == 0) zs[warp] = z;
    }
    __syncthreads();

    for (int h = tid; h < H_SZ; h += 256) {
        float acc = post_b[h];
#pragma unroll
        for (int q = 0; q < NQ; q++) acc += zs[q] * post_w[h * NQ + q];
        out[(size_t)b * N_SZ * H_SZ + h] = acc;
    }
}

// ---------------------------------------------------------------------------
extern "C" void kernel_launch(void* const* d_in, const int* in_sizes, int n_in,
                              void* d_out, int out_size) {
    const float* x      = (const float*)d_in[0];
    const float* adj    = (const float*)d_in[1];
    const float* Wg     = (const float*)d_in[2];
    const float* bg     = (const float*)d_in[3];
    const float* pre_w  = (const float*)d_in[4];
    const float* pre_b  = (const float*)d_in[5];
    const float* post_w = (const float*)d_in[6];
    const float* post_b = (const float*)d_in[7];
    const float* qw     = (const float*)d_in[8];
    float* out = (float*)d_out;

    cudaFuncSetAttribute(gemm1_mma_kernel,
                         cudaFuncAttributeMaxDynamicSharedMemorySize, SMEM_GEMM);
    cudaFuncSetAttribute(gemm2_mma_kernel,
                         cudaFuncAttributeMaxDynamicSharedMemorySize, SMEM_GEMM);

    conv_x_kernel<<<(B_SZ * N_SZ * H_SZ) / (256 * 8), 256>>>(x);
    conv_small_kernel<<<dim3(256, 2), 256>>>(adj, Wg);
    gemm1_mma_kernel<<<NPERSIST, NTHREADS, SMEM_GEMM>>>();
    gemm2_mma_kernel<<<NPERSIST, NTHREADS, SMEM_GEMM>>>(bg, out);
    quantum_kernel<<<B_SZ, 256>>>(pre_w, pre_b, post_w, post_b, qw, out);
}